// round 14
// baseline (speedup 1.0000x reference)
#include <cuda_runtime.h>
#include <cuda_fp16.h>
#include <math.h>
#include <stdint.h>

#define N_NODES 50000
#define N_EDGES 800000
#define IN_F    128
#define OUT_F   32
#define HEADS   4
#define HO      128            // HEADS * OUT_F
#define NEG_SLOPE 0.2f
#define EPS_F 1e-10f

#define SCAN_B 256
#define N_SCAN_BLOCKS ((N_NODES + SCAN_B - 1) / SCAN_B)   // 196

#define BM 256
#define NB_GEMM ((N_NODES + BM - 1) / BM)                 // 196
#define NB_HIST ((N_EDGES + 255) / 256)                   // 3125

// smem: X planes [256][136] fp16 (hi/lo) + W plane [128][136] fp16
#define SM_STRIDE 136
#define SMX_PLANE (256 * SM_STRIDE)                       // 34816 halves
#define SMW_PLANE (128 * SM_STRIDE)                       // 17408 halves
#define SMEM_GEMM_BYTES ((2 * SMX_PLANE + SMW_PLANE) * 2) // 174080

// ---------------- scratch (static device allocations) ----------------------
__device__ __half g_h16[N_NODES * HO];     // projected features, fp16 [N, H*O]
__device__ float g_es[N_NODES * HEADS];    // per-node src logits (fp32)
__device__ float g_ed[N_NODES * HEADS];    // per-node dst logits (fp32)
__device__ int   g_count[N_NODES];         // zeroed at load; re-zeroed by scan
__device__ int   g_offset[N_NODES + 1];
__device__ int   g_cursor[N_NODES];
__device__ int   g_srcsorted[N_EDGES];
// decoupled-lookback state (zeroed at load; re-zeroed by k_scatter)
__device__ int                g_ticket;
__device__ unsigned long long g_state[N_SCAN_BLOCKS];   // (sum<<2)|status

// ---------------- fp16 mma helper -------------------------------------------
__device__ __forceinline__ void mma_f16(float c[4],
    uint32_t a0, uint32_t a1, uint32_t a2, uint32_t a3,
    uint32_t b0, uint32_t b1)
{
    asm volatile(
        "mma.sync.aligned.m16n8k16.row.col.f32.f16.f16.f32 "
        "{%0,%1,%2,%3},{%4,%5,%6,%7},{%8,%9},{%0,%1,%2,%3};\n"
        : "+f"(c[0]), "+f"(c[1]), "+f"(c[2]), "+f"(c[3])
        : "r"(a0), "r"(a1), "r"(a2), "r"(a3), "r"(b0), "r"(b1));
}

// ---------------- K1: fp16x2 tensor GEMM h = x @ Wc + fused logits ----------
// 512 thr = 16 warps in 8x2 grid; block tile 256x128; warp tile 32x64.
// C = (Xhi + Xlo) * W_fp16 : 2 MMAs per logical tile (W error 2^-12).
__global__ void __launch_bounds__(512) k_gemm(
    const float* __restrict__ x,
    const float* __restrict__ W,
    const float* __restrict__ a_src,
    const float* __restrict__ a_dst)
{
    extern __shared__ __half sm[];
    __half* Xhi = sm;
    __half* Xlo = sm + SMX_PLANE;
    __half* Wh  = sm + 2 * SMX_PLANE;      // [n][k], swizzled ks = k^((n&3)<<4)

    int tid  = threadIdx.x;
    int w    = tid >> 5;
    int lane = tid & 31;
    int g    = lane >> 2;
    int t    = lane & 3;
    int wm   = w >> 1;       // warp row 0..7 (32 rows each)
    int wn   = w & 1;        // warp col 0..1 (64 cols each)
    int m0   = blockIdx.x * BM;

    // ---- stage X (256 rows x 128 k), split to fp16 hi/lo ----
    #pragma unroll
    for (int i = 0; i < 16; ++i) {
        int f = tid + i * 512;          // float4 id, 0..8191
        int r = f >> 5;
        int c = (f & 31) * 4;
        int grow = m0 + r;
        float4 v = make_float4(0.f, 0.f, 0.f, 0.f);
        if (grow < N_NODES) v = *(const float4*)&x[grow * IN_F + c];
        float vv[4] = {v.x, v.y, v.z, v.w};
        __half hb[4], lb[4];
        #pragma unroll
        for (int j = 0; j < 4; ++j) {
            hb[j] = __float2half_rn(vv[j]);
            lb[j] = __float2half_rn(vv[j] - __half2float(hb[j]));
        }
        __half2 ph0(hb[0], hb[1]), ph1(hb[2], hb[3]);
        __half2 pl0(lb[0], lb[1]), pl1(lb[2], lb[3]);
        uint2 uh = make_uint2(reinterpret_cast<uint32_t&>(ph0),
                              reinterpret_cast<uint32_t&>(ph1));
        uint2 ul = make_uint2(reinterpret_cast<uint32_t&>(pl0),
                              reinterpret_cast<uint32_t&>(pl1));
        *(uint2*)&Xhi[r * SM_STRIDE + c] = uh;
        *(uint2*)&Xlo[r * SM_STRIDE + c] = ul;
    }
    // ---- stage W (16384 floats), inline fp16 convert, [n][k] swizzled ----
    // idx = head*4096 + k*32 + o; float4 covers 4 consecutive o (4 n-rows).
    #pragma unroll
    for (int i = 0; i < 8; ++i) {
        int f4 = tid + i * 512;         // 0..4095
        int idx = f4 * 4;
        float4 v = *(const float4*)&W[idx];
        int o  = idx & 31;
        int k  = (idx >> 5) & 127;
        int nb = (idx >> 12) * 32 + o;  // n for j=0 (nb % 4 == 0)
        Wh[(nb + 0) * SM_STRIDE + k]             = __float2half_rn(v.x);
        Wh[(nb + 1) * SM_STRIDE + (k ^ 16)]      = __float2half_rn(v.y);
        Wh[(nb + 2) * SM_STRIDE + (k ^ 32)]      = __float2half_rn(v.z);
        Wh[(nb + 3) * SM_STRIDE + (k ^ 48)]      = __float2half_rn(v.w);
    }
    __syncthreads();

    float C[2][8][4];
    #pragma unroll
    for (int ms = 0; ms < 2; ++ms)
        #pragma unroll
        for (int nt = 0; nt < 8; ++nt)
            #pragma unroll
            for (int j = 0; j < 4; ++j) C[ms][nt][j] = 0.0f;

    // ---- mainloop: 8 k-chunks of 16; LDS + MMA only ----
    #pragma unroll
    for (int kc = 0; kc < 8; ++kc) {
        int kw = kc * 8 + t;            // uint32 (half2) index
        uint32_t axh[2][4], axl[2][4];
        #pragma unroll
        for (int ms = 0; ms < 2; ++ms) {
            int r0 = wm * 32 + ms * 16 + g;
            const uint32_t* ph0 = (const uint32_t*)(Xhi + r0 * SM_STRIDE);
            const uint32_t* ph8 = (const uint32_t*)(Xhi + (r0 + 8) * SM_STRIDE);
            const uint32_t* pl0 = (const uint32_t*)(Xlo + r0 * SM_STRIDE);
            const uint32_t* pl8 = (const uint32_t*)(Xlo + (r0 + 8) * SM_STRIDE);
            axh[ms][0] = ph0[kw];     axh[ms][1] = ph8[kw];
            axh[ms][2] = ph0[kw + 4]; axh[ms][3] = ph8[kw + 4];
            axl[ms][0] = pl0[kw];     axl[ms][1] = pl8[kw];
            axl[ms][2] = pl0[kw + 4]; axl[ms][3] = pl8[kw + 4];
        }
        #pragma unroll
        for (int nt = 0; nt < 8; ++nt) {
            int n = wn * 64 + nt * 8 + g;
            int kws = kw ^ ((n & 3) << 3);     // swizzled word index
            const uint32_t* qh = (const uint32_t*)(Wh + n * SM_STRIDE);
            uint32_t bh0 = qh[kws], bh1 = qh[kws + 4];
            #pragma unroll
            for (int ms = 0; ms < 2; ++ms) {
                mma_f16(C[ms][nt], axh[ms][0], axh[ms][1], axh[ms][2], axh[ms][3], bh0, bh1);
                mma_f16(C[ms][nt], axl[ms][0], axl[ms][1], axl[ms][2], axl[ms][3], bh0, bh1);
            }
        }
    }

    // ---- epilogue: fp16 h store + fused per-head logits ----
    float psA[2][2], pdA[2][2], psB[2][2], pdB[2][2];
    #pragma unroll
    for (int ms = 0; ms < 2; ++ms)
        #pragma unroll
        for (int hl = 0; hl < 2; ++hl)
            psA[ms][hl] = pdA[ms][hl] = psB[ms][hl] = pdB[ms][hl] = 0.f;

    #pragma unroll
    for (int nt = 0; nt < 8; ++nt) {
        int hl = nt >> 2;
        int c0 = wn * 64 + nt * 8 + 2 * t;
        float as0 = a_src[c0], as1 = a_src[c0 + 1];
        float ad0 = a_dst[c0], ad1 = a_dst[c0 + 1];
        #pragma unroll
        for (int ms = 0; ms < 2; ++ms) {
            int row0 = m0 + wm * 32 + ms * 16 + g;
            psA[ms][hl] += C[ms][nt][0] * as0 + C[ms][nt][1] * as1;
            pdA[ms][hl] += C[ms][nt][0] * ad0 + C[ms][nt][1] * ad1;
            psB[ms][hl] += C[ms][nt][2] * as0 + C[ms][nt][3] * as1;
            pdB[ms][hl] += C[ms][nt][2] * ad0 + C[ms][nt][3] * ad1;
            if (row0 < N_NODES)
                *(__half2*)&g_h16[row0 * HO + c0] =
                    __floats2half2_rn(C[ms][nt][0], C[ms][nt][1]);
            if (row0 + 8 < N_NODES)
                *(__half2*)&g_h16[(row0 + 8) * HO + c0] =
                    __floats2half2_rn(C[ms][nt][2], C[ms][nt][3]);
        }
    }
    #pragma unroll
    for (int ms = 0; ms < 2; ++ms)
        #pragma unroll
        for (int hl = 0; hl < 2; ++hl) {
            psA[ms][hl] += __shfl_xor_sync(0xffffffffu, psA[ms][hl], 1);
            psA[ms][hl] += __shfl_xor_sync(0xffffffffu, psA[ms][hl], 2);
            pdA[ms][hl] += __shfl_xor_sync(0xffffffffu, pdA[ms][hl], 1);
            pdA[ms][hl] += __shfl_xor_sync(0xffffffffu, pdA[ms][hl], 2);
            psB[ms][hl] += __shfl_xor_sync(0xffffffffu, psB[ms][hl], 1);
            psB[ms][hl] += __shfl_xor_sync(0xffffffffu, psB[ms][hl], 2);
            pdB[ms][hl] += __shfl_xor_sync(0xffffffffu, pdB[ms][hl], 1);
            pdB[ms][hl] += __shfl_xor_sync(0xffffffffu, pdB[ms][hl], 2);
        }
    if (t == 0) {
        #pragma unroll
        for (int ms = 0; ms < 2; ++ms) {
            int row0 = m0 + wm * 32 + ms * 16 + g;
            int row1 = row0 + 8;
            if (row0 < N_NODES) {
                *(float2*)&g_es[row0 * HEADS + wn * 2] = make_float2(psA[ms][0], psA[ms][1]);
                *(float2*)&g_ed[row0 * HEADS + wn * 2] = make_float2(pdA[ms][0], pdA[ms][1]);
            }
            if (row1 < N_NODES) {
                *(float2*)&g_es[row1 * HEADS + wn * 2] = make_float2(psB[ms][0], psB[ms][1]);
                *(float2*)&g_ed[row1 * HEADS + wn * 2] = make_float2(pdB[ms][0], pdB[ms][1]);
            }
        }
    }
}

// ---------------- K2: degree histogram (side stream) ------------------------
__global__ void k_hist(const int* __restrict__ ei) {
    int e = blockIdx.x * blockDim.x + threadIdx.x;
    if (e < N_EDGES) atomicAdd(&g_count[ei[N_EDGES + e]], 1);
}

// ---------------- K3: single-kernel decoupled-lookback scan ------------------
__global__ void __launch_bounds__(SCAN_B) k_scanlb() {
    __shared__ int warp_sums[8];
    __shared__ int sh_bid;
    __shared__ long long sh_prefix;

    if (threadIdx.x == 0) sh_bid = atomicAdd(&g_ticket, 1);
    __syncthreads();
    int bid = sh_bid;

    int i = bid * SCAN_B + threadIdx.x;
    int lane = threadIdx.x & 31, wid = threadIdx.x >> 5;
    int c = (i < N_NODES) ? g_count[i] : 0;
    if (i < N_NODES) g_count[i] = 0;             // restore for next replay
    int v = c;
    #pragma unroll
    for (int d = 1; d < 32; d <<= 1) {
        int u = __shfl_up_sync(0xffffffffu, v, d);
        if (lane >= d) v += u;
    }
    if (lane == 31) warp_sums[wid] = v;
    __syncthreads();
    if (wid == 0) {
        int s = (lane < 8) ? warp_sums[lane] : 0;
        #pragma unroll
        for (int d = 1; d < 8; d <<= 1) {
            int u = __shfl_up_sync(0xffffffffu, s, d);
            if (lane >= d) s += u;
        }
        if (lane < 8) warp_sums[lane] = s;
    }
    __syncthreads();
    int incl = v + (wid ? warp_sums[wid - 1] : 0);
    long long T = warp_sums[7];

    if (threadIdx.x == 0) {
        if (bid == 0) {
            atomicExch(&g_state[0], ((unsigned long long)T << 2) | 2ULL);
            sh_prefix = 0;
        } else {
            atomicExch(&g_state[bid], ((unsigned long long)T << 2) | 1ULL);
            long long exc = 0;
            int pred = bid - 1;
            while (pred >= 0) {
                unsigned long long s;
                do { s = atomicAdd(&g_state[pred], 0ULL); } while ((s & 3ULL) == 0ULL);
                exc += (long long)(s >> 2);
                if ((s & 3ULL) == 2ULL) break;
                --pred;
            }
            atomicExch(&g_state[bid], ((unsigned long long)(exc + T) << 2) | 2ULL);
            sh_prefix = exc;
        }
    }
    __syncthreads();
    int pre = (int)sh_prefix;
    if (i < N_NODES) {
        int off = pre + incl - c;
        g_offset[i] = off;
        g_cursor[i] = off;
    }
    if (i == 0) g_offset[N_NODES] = N_EDGES;
}

// ---------------- K4: bucket edges by dst + reset lookback state -------------
__global__ void k_scatter(const int* __restrict__ ei) {
    if (blockIdx.x == 0) {
        if (threadIdx.x < N_SCAN_BLOCKS) g_state[threadIdx.x] = 0ULL;
        if (threadIdx.x == 0) g_ticket = 0;
    }
    int e = blockIdx.x * blockDim.x + threadIdx.x;
    if (e < N_EDGES) {
        int src = ei[e];
        int dst = ei[N_EDGES + e];
        int pos = atomicAdd(&g_cursor[dst], 1);
        g_srcsorted[pos] = src;
    }
}

// ---------------- K5: softmax + aggregation (half-warp/edge, ILP-4) ----------
// 16 lanes per edge, uint4 h loads; 4 edges per half-warp per iteration,
// all-scalar state (no local arrays -> no spill).
__global__ void __launch_bounds__(256) k_aggregate(float* __restrict__ out)
{
    int warp = threadIdx.x >> 5;
    int lane = threadIdx.x & 31;
    int n = blockIdx.x * 8 + warp;
    if (n >= N_NODES) return;

    int half = lane >> 4;
    int sub  = lane & 15;
    int head = sub >> 2;

    int beg = g_offset[n];
    int end = g_offset[n + 1];

    float4 edn = *(const float4*)&g_ed[n * HEADS];
    float edh = (head == 0) ? edn.x : (head == 1) ? edn.y : (head == 2) ? edn.z : edn.w;

    float acc0 = 0.f, acc1 = 0.f, acc2 = 0.f, acc3 = 0.f;
    float acc4 = 0.f, acc5 = 0.f, acc6 = 0.f, acc7 = 0.f;
    float ssum = 0.f;

    for (int e = beg; e < end; e += 8) {
        int i0 = e + half;
        int i1 = e + 2 + half;
        int i2 = e + 4 + half;
        int i3 = e + 6 + half;
        bool b0 = i0 < end, b1 = i1 < end, b2 = i2 < end, b3 = i3 < end;
        int s0 = g_srcsorted[b0 ? i0 : beg];
        int s1 = g_srcsorted[b1 ? i1 : beg];
        int s2 = g_srcsorted[b2 ? i2 : beg];
        int s3 = g_srcsorted[b3 ? i3 : beg];
        float e0 = g_es[s0 * HEADS + head];
        float e1 = g_es[s1 * HEADS + head];
        float e2 = g_es[s2 * HEADS + head];
        float e3 = g_es[s3 * HEADS + head];
        uint4 u0 = *(const uint4*)&g_h16[s0 * HO + sub * 8];
        uint4 u1 = *(const uint4*)&g_h16[s1 * HO + sub * 8];
        uint4 u2 = *(const uint4*)&g_h16[s2 * HO + sub * 8];
        uint4 u3 = *(const uint4*)&g_h16[s3 * HO + sub * 8];

        e0 += edh; e0 = e0 >= 0.f ? e0 : NEG_SLOPE * e0;
        e1 += edh; e1 = e1 >= 0.f ? e1 : NEG_SLOPE * e1;
        e2 += edh; e2 = e2 >= 0.f ? e2 : NEG_SLOPE * e2;
        e3 += edh; e3 = e3 >= 0.f ? e3 : NEG_SLOPE * e3;
        float w0 = b0 ? __expf(e0) : 0.f;
        float w1 = b1 ? __expf(e1) : 0.f;
        float w2 = b2 ? __expf(e2) : 0.f;
        float w3 = b3 ? __expf(e3) : 0.f;
        ssum += (w0 + w1) + (w2 + w3);

        float2 f;
        f = __half22float2(*(__half2*)&u0.x); acc0 = fmaf(w0, f.x, acc0); acc1 = fmaf(w0, f.y, acc1);
        f = __half22float2(*(__half2*)&u0.y); acc2 = fmaf(w0, f.x, acc2); acc3 = fmaf(w0, f.y, acc3);
        f = __half22float2(*(__half2*)&u0.z); acc4 = fmaf(w0, f.x, acc4); acc5 = fmaf(w0, f.y, acc5);
        f = __half22float2(*(__half2*)&u0.w); acc6 = fmaf(w0, f.x, acc6); acc7 = fmaf(w0, f.y, acc7);
        f = __half22float2(*(__half2*)&u1.x); acc0 = fmaf(w1, f.x, acc0); acc1 = fmaf(w1, f.y, acc1);
        f = __half22float2(*(__half2*)&u1.y); acc2 = fmaf(w1, f.x, acc2); acc3 = fmaf(w1, f.y, acc3);
        f = __half22float2(*(__half2*)&u1.z); acc4 = fmaf(w1, f.x, acc4); acc5 = fmaf(w1, f.y, acc5);
        f = __half22float2(*(__half2*)&u1.w); acc6 = fmaf(w1, f.x, acc6); acc7 = fmaf(w1, f.y, acc7);
        f = __half22float2(*(__half2*)&u2.x); acc0 = fmaf(w2, f.x, acc0); acc1 = fmaf(w2, f.y, acc1);
        f = __half22float2(*(__half2*)&u2.y); acc2 = fmaf(w2, f.x, acc2); acc3 = fmaf(w2, f.y, acc3);
        f = __half22float2(*(__half2*)&u2.z); acc4 = fmaf(w2, f.x, acc4); acc5 = fmaf(w2, f.y, acc5);
        f = __half22float2(*(__half2*)&u2.w); acc6 = fmaf(w2, f.x, acc6); acc7 = fmaf(w2, f.y, acc7);
        f = __half22float2(*(__half2*)&u3.x); acc0 = fmaf(w3, f.x, acc0); acc1 = fmaf(w3, f.y, acc1);
        f = __half22float2(*(__half2*)&u3.y); acc2 = fmaf(w3, f.x, acc2); acc3 = fmaf(w3, f.y, acc3);
        f = __half22float2(*(__half2*)&u3.z); acc4 = fmaf(w3, f.x, acc4); acc5 = fmaf(w3, f.y, acc5);
        f = __half22float2(*(__half2*)&u3.w); acc6 = fmaf(w3, f.x, acc6); acc7 = fmaf(w3, f.y, acc7);
    }

    // combine the two halves
    acc0 += __shfl_xor_sync(0xffffffffu, acc0, 16);
    acc1 += __shfl_xor_sync(0xffffffffu, acc1, 16);
    acc2 += __shfl_xor_sync(0xffffffffu, acc2, 16);
    acc3 += __shfl_xor_sync(0xffffffffu, acc3, 16);
    acc4 += __shfl_xor_sync(0xffffffffu, acc4, 16);
    acc5 += __shfl_xor_sync(0xffffffffu, acc5, 16);
    acc6 += __shfl_xor_sync(0xffffffffu, acc6, 16);
    acc7 += __shfl_xor_sync(0xffffffffu, acc7, 16);
    ssum += __shfl_xor_sync(0xffffffffu, ssum, 16);

    float inv = 1.0f / (ssum + EPS_F);
    if (half == 0) {
        float4 r0 = make_float4(acc0 * inv, acc1 * inv, acc2 * inv, acc3 * inv);
        float4 r1 = make_float4(acc4 * inv, acc5 * inv, acc6 * inv, acc7 * inv);
        *(float4*)&out[n * HO + sub * 8]     = r0;
        *(float4*)&out[n * HO + sub * 8 + 4] = r1;
    }
}

// ---------------- launch ------------------------------------------------------
extern "C" void kernel_launch(void* const* d_in, const int* in_sizes, int n_in,
                              void* d_out, int out_size)
{
    const float* x     = (const float*)d_in[0];
    const int*   ei    = (const int*)  d_in[1];
    const float* W     = (const float*)d_in[2];
    const float* a_src = (const float*)d_in[3];
    const float* a_dst = (const float*)d_in[4];
    float* out = (float*)d_out;

    cudaFuncSetAttribute(k_gemm, cudaFuncAttributeMaxDynamicSharedMemorySize,
                         SMEM_GEMM_BYTES);

    cudaStream_t s1;
    cudaStreamCreateWithFlags(&s1, cudaStreamNonBlocking);
    cudaEvent_t ev0, ev1;
    cudaEventCreateWithFlags(&ev0, cudaEventDisableTiming);
    cudaEventCreateWithFlags(&ev1, cudaEventDisableTiming);

    cudaEventRecord(ev0, 0);
    cudaStreamWaitEvent(s1, ev0, 0);

    // launch 1: projection GEMM (+logits) on main stream
    k_gemm<<<NB_GEMM, 512, SMEM_GEMM_BYTES>>>(x, W, a_src, a_dst);

    // launches 2-4: CSR build (side stream, concurrent with GEMM)
    k_hist   <<<NB_HIST, 256, 0, s1>>>(ei);
    k_scanlb <<<N_SCAN_BLOCKS, SCAN_B, 0, s1>>>();
    k_scatter<<<(N_EDGES + 255) / 256, 256, 0, s1>>>(ei);   // 4th: profiled
    cudaEventRecord(ev1, s1);

    // join, then launch 5: aggregate
    cudaStreamWaitEvent(0, ev1, 0);
    k_aggregate<<<(N_NODES + 7) / 8, 256>>>(out);

    cudaEventDestroy(ev0);
    cudaEventDestroy(ev1);
    cudaStreamDestroy(s1);
}

// round 16
// speedup vs baseline: 1.0274x; 1.0274x over previous
#include <cuda_runtime.h>
#include <cuda_fp16.h>
#include <math.h>
#include <stdint.h>

#define N_NODES 50000
#define N_EDGES 800000
#define IN_F    128
#define OUT_F   32
#define HEADS   4
#define HO      128            // HEADS * OUT_F
#define NEG_SLOPE 0.2f
#define EPS_F 1e-10f

#define SCAN_B 256
#define N_SCAN_BLOCKS ((N_NODES + SCAN_B - 1) / SCAN_B)   // 196

#define BM 256
#define NB_GEMM ((N_NODES + BM - 1) / BM)                 // 196
#define NB_HIST ((N_EDGES + 255) / 256)                   // 3125

// smem: X planes [256][136] fp16 (hi/lo) + W plane [128][136] fp16
#define SM_STRIDE 136
#define SMX_PLANE (256 * SM_STRIDE)                       // 34816 halves
#define SMW_PLANE (128 * SM_STRIDE)                       // 17408 halves
#define SMEM_GEMM_BYTES ((2 * SMX_PLANE + SMW_PLANE) * 2) // 174080

// ---------------- scratch (static device allocations) ----------------------
__device__ __half g_h16[N_NODES * HO];     // projected features, fp16 [N, H*O]
__device__ float g_es[N_NODES * HEADS];    // per-node src logits (fp32)
__device__ float g_ed[N_NODES * HEADS];    // per-node dst logits (fp32)
__device__ int   g_count[N_NODES];         // zeroed at load; re-zeroed by scan
__device__ int   g_offset[N_NODES + 1];
__device__ int   g_rank[N_EDGES];          // edge's arrival rank within its dst
__device__ int   g_srcsorted[N_EDGES];
// decoupled-lookback state (zeroed at load; re-zeroed by k_scatter)
__device__ int                g_ticket;
__device__ unsigned long long g_state[N_SCAN_BLOCKS];   // (sum<<2)|status

// ---------------- fp16 mma helper -------------------------------------------
__device__ __forceinline__ void mma_f16(float c[4],
    uint32_t a0, uint32_t a1, uint32_t a2, uint32_t a3,
    uint32_t b0, uint32_t b1)
{
    asm volatile(
        "mma.sync.aligned.m16n8k16.row.col.f32.f16.f16.f32 "
        "{%0,%1,%2,%3},{%4,%5,%6,%7},{%8,%9},{%0,%1,%2,%3};\n"
        : "+f"(c[0]), "+f"(c[1]), "+f"(c[2]), "+f"(c[3])
        : "r"(a0), "r"(a1), "r"(a2), "r"(a3), "r"(b0), "r"(b1));
}

// ---------------- K1: fp16x2 tensor GEMM h = x @ Wc + fused logits ----------
// 512 thr = 16 warps in 8x2 grid; block tile 256x128; warp tile 32x64.
// C = (Xhi + Xlo) * W_fp16 : 2 MMAs per logical tile.
__global__ void __launch_bounds__(512) k_gemm(
    const float* __restrict__ x,
    const float* __restrict__ W,
    const float* __restrict__ a_src,
    const float* __restrict__ a_dst)
{
    extern __shared__ __half sm[];
    __half* Xhi = sm;
    __half* Xlo = sm + SMX_PLANE;
    __half* Wh  = sm + 2 * SMX_PLANE;      // [n][k], swizzled ks = k^((n&3)<<4)

    int tid  = threadIdx.x;
    int w    = tid >> 5;
    int lane = tid & 31;
    int g    = lane >> 2;
    int t    = lane & 3;
    int wm   = w >> 1;
    int wn   = w & 1;
    int m0   = blockIdx.x * BM;

    // ---- stage X (256 rows x 128 k), split to fp16 hi/lo ----
    #pragma unroll
    for (int i = 0; i < 16; ++i) {
        int f = tid + i * 512;
        int r = f >> 5;
        int c = (f & 31) * 4;
        int grow = m0 + r;
        float4 v = make_float4(0.f, 0.f, 0.f, 0.f);
        if (grow < N_NODES) v = *(const float4*)&x[grow * IN_F + c];
        float vv[4] = {v.x, v.y, v.z, v.w};
        __half hb[4], lb[4];
        #pragma unroll
        for (int j = 0; j < 4; ++j) {
            hb[j] = __float2half_rn(vv[j]);
            lb[j] = __float2half_rn(vv[j] - __half2float(hb[j]));
        }
        __half2 ph0(hb[0], hb[1]), ph1(hb[2], hb[3]);
        __half2 pl0(lb[0], lb[1]), pl1(lb[2], lb[3]);
        uint2 uh = make_uint2(reinterpret_cast<uint32_t&>(ph0),
                              reinterpret_cast<uint32_t&>(ph1));
        uint2 ul = make_uint2(reinterpret_cast<uint32_t&>(pl0),
                              reinterpret_cast<uint32_t&>(pl1));
        *(uint2*)&Xhi[r * SM_STRIDE + c] = uh;
        *(uint2*)&Xlo[r * SM_STRIDE + c] = ul;
    }
    // ---- stage W, inline fp16 convert, [n][k] swizzled ----
    #pragma unroll
    for (int i = 0; i < 8; ++i) {
        int f4 = tid + i * 512;
        int idx = f4 * 4;
        float4 v = *(const float4*)&W[idx];
        int o  = idx & 31;
        int k  = (idx >> 5) & 127;
        int nb = (idx >> 12) * 32 + o;
        Wh[(nb + 0) * SM_STRIDE + k]        = __float2half_rn(v.x);
        Wh[(nb + 1) * SM_STRIDE + (k ^ 16)] = __float2half_rn(v.y);
        Wh[(nb + 2) * SM_STRIDE + (k ^ 32)] = __float2half_rn(v.z);
        Wh[(nb + 3) * SM_STRIDE + (k ^ 48)] = __float2half_rn(v.w);
    }
    __syncthreads();

    float C[2][8][4];
    #pragma unroll
    for (int ms = 0; ms < 2; ++ms)
        #pragma unroll
        for (int nt = 0; nt < 8; ++nt)
            #pragma unroll
            for (int j = 0; j < 4; ++j) C[ms][nt][j] = 0.0f;

    #pragma unroll
    for (int kc = 0; kc < 8; ++kc) {
        int kw = kc * 8 + t;
        uint32_t axh[2][4], axl[2][4];
        #pragma unroll
        for (int ms = 0; ms < 2; ++ms) {
            int r0 = wm * 32 + ms * 16 + g;
            const uint32_t* ph0 = (const uint32_t*)(Xhi + r0 * SM_STRIDE);
            const uint32_t* ph8 = (const uint32_t*)(Xhi + (r0 + 8) * SM_STRIDE);
            const uint32_t* pl0 = (const uint32_t*)(Xlo + r0 * SM_STRIDE);
            const uint32_t* pl8 = (const uint32_t*)(Xlo + (r0 + 8) * SM_STRIDE);
            axh[ms][0] = ph0[kw];     axh[ms][1] = ph8[kw];
            axh[ms][2] = ph0[kw + 4]; axh[ms][3] = ph8[kw + 4];
            axl[ms][0] = pl0[kw];     axl[ms][1] = pl8[kw];
            axl[ms][2] = pl0[kw + 4]; axl[ms][3] = pl8[kw + 4];
        }
        #pragma unroll
        for (int nt = 0; nt < 8; ++nt) {
            int n = wn * 64 + nt * 8 + g;
            int kws = kw ^ ((n & 3) << 3);
            const uint32_t* qh = (const uint32_t*)(Wh + n * SM_STRIDE);
            uint32_t bh0 = qh[kws], bh1 = qh[kws + 4];
            #pragma unroll
            for (int ms = 0; ms < 2; ++ms) {
                mma_f16(C[ms][nt], axh[ms][0], axh[ms][1], axh[ms][2], axh[ms][3], bh0, bh1);
                mma_f16(C[ms][nt], axl[ms][0], axl[ms][1], axl[ms][2], axl[ms][3], bh0, bh1);
            }
        }
    }

    // ---- epilogue: fp16 h store + fused per-head logits ----
    float psA[2][2], pdA[2][2], psB[2][2], pdB[2][2];
    #pragma unroll
    for (int ms = 0; ms < 2; ++ms)
        #pragma unroll
        for (int hl = 0; hl < 2; ++hl)
            psA[ms][hl] = pdA[ms][hl] = psB[ms][hl] = pdB[ms][hl] = 0.f;

    #pragma unroll
    for (int nt = 0; nt < 8; ++nt) {
        int hl = nt >> 2;
        int c0 = wn * 64 + nt * 8 + 2 * t;
        float as0 = a_src[c0], as1 = a_src[c0 + 1];
        float ad0 = a_dst[c0], ad1 = a_dst[c0 + 1];
        #pragma unroll
        for (int ms = 0; ms < 2; ++ms) {
            int row0 = m0 + wm * 32 + ms * 16 + g;
            psA[ms][hl] += C[ms][nt][0] * as0 + C[ms][nt][1] * as1;
            pdA[ms][hl] += C[ms][nt][0] * ad0 + C[ms][nt][1] * ad1;
            psB[ms][hl] += C[ms][nt][2] * as0 + C[ms][nt][3] * as1;
            pdB[ms][hl] += C[ms][nt][2] * ad0 + C[ms][nt][3] * ad1;
            if (row0 < N_NODES)
                *(__half2*)&g_h16[row0 * HO + c0] =
                    __floats2half2_rn(C[ms][nt][0], C[ms][nt][1]);
            if (row0 + 8 < N_NODES)
                *(__half2*)&g_h16[(row0 + 8) * HO + c0] =
                    __floats2half2_rn(C[ms][nt][2], C[ms][nt][3]);
        }
    }
    #pragma unroll
    for (int ms = 0; ms < 2; ++ms)
        #pragma unroll
        for (int hl = 0; hl < 2; ++hl) {
            psA[ms][hl] += __shfl_xor_sync(0xffffffffu, psA[ms][hl], 1);
            psA[ms][hl] += __shfl_xor_sync(0xffffffffu, psA[ms][hl], 2);
            pdA[ms][hl] += __shfl_xor_sync(0xffffffffu, pdA[ms][hl], 1);
            pdA[ms][hl] += __shfl_xor_sync(0xffffffffu, pdA[ms][hl], 2);
            psB[ms][hl] += __shfl_xor_sync(0xffffffffu, psB[ms][hl], 1);
            psB[ms][hl] += __shfl_xor_sync(0xffffffffu, psB[ms][hl], 2);
            pdB[ms][hl] += __shfl_xor_sync(0xffffffffu, pdB[ms][hl], 1);
            pdB[ms][hl] += __shfl_xor_sync(0xffffffffu, pdB[ms][hl], 2);
        }
    if (t == 0) {
        #pragma unroll
        for (int ms = 0; ms < 2; ++ms) {
            int row0 = m0 + wm * 32 + ms * 16 + g;
            int row1 = row0 + 8;
            if (row0 < N_NODES) {
                *(float2*)&g_es[row0 * HEADS + wn * 2] = make_float2(psA[ms][0], psA[ms][1]);
                *(float2*)&g_ed[row0 * HEADS + wn * 2] = make_float2(pdA[ms][0], pdA[ms][1]);
            }
            if (row1 < N_NODES) {
                *(float2*)&g_es[row1 * HEADS + wn * 2] = make_float2(psB[ms][0], psB[ms][1]);
                *(float2*)&g_ed[row1 * HEADS + wn * 2] = make_float2(pdB[ms][0], pdB[ms][1]);
            }
        }
    }
}

// ---------------- K2: degree histogram + per-edge rank ----------------------
// The atomic's return value IS the edge's rank within its dst segment.
__global__ void k_hist(const int* __restrict__ ei) {
    int e = blockIdx.x * blockDim.x + threadIdx.x;
    if (e < N_EDGES) {
        int dst = ei[N_EDGES + e];
        g_rank[e] = atomicAdd(&g_count[dst], 1);
    }
}

// ---------------- K3: single-kernel decoupled-lookback scan ------------------
__global__ void __launch_bounds__(SCAN_B) k_scanlb() {
    __shared__ int warp_sums[8];
    __shared__ int sh_bid;
    __shared__ long long sh_prefix;

    if (threadIdx.x == 0) sh_bid = atomicAdd(&g_ticket, 1);
    __syncthreads();
    int bid = sh_bid;

    int i = bid * SCAN_B + threadIdx.x;
    int lane = threadIdx.x & 31, wid = threadIdx.x >> 5;
    int c = (i < N_NODES) ? g_count[i] : 0;
    if (i < N_NODES) g_count[i] = 0;             // restore for next replay
    int v = c;
    #pragma unroll
    for (int d = 1; d < 32; d <<= 1) {
        int u = __shfl_up_sync(0xffffffffu, v, d);
        if (lane >= d) v += u;
    }
    if (lane == 31) warp_sums[wid] = v;
    __syncthreads();
    if (wid == 0) {
        int s = (lane < 8) ? warp_sums[lane] : 0;
        #pragma unroll
        for (int d = 1; d < 8; d <<= 1) {
            int u = __shfl_up_sync(0xffffffffu, s, d);
            if (lane >= d) s += u;
        }
        if (lane < 8) warp_sums[lane] = s;
    }
    __syncthreads();
    int incl = v + (wid ? warp_sums[wid - 1] : 0);
    long long T = warp_sums[7];

    if (threadIdx.x == 0) {
        if (bid == 0) {
            atomicExch(&g_state[0], ((unsigned long long)T << 2) | 2ULL);
            sh_prefix = 0;
        } else {
            atomicExch(&g_state[bid], ((unsigned long long)T << 2) | 1ULL);
            long long exc = 0;
            int pred = bid - 1;
            while (pred >= 0) {
                unsigned long long s;
                do { s = atomicAdd(&g_state[pred], 0ULL); } while ((s & 3ULL) == 0ULL);
                exc += (long long)(s >> 2);
                if ((s & 3ULL) == 2ULL) break;
                --pred;
            }
            atomicExch(&g_state[bid], ((unsigned long long)(exc + T) << 2) | 2ULL);
            sh_prefix = exc;
        }
    }
    __syncthreads();
    int pre = (int)sh_prefix;
    if (i < N_NODES) g_offset[i] = pre + incl - c;
    if (i == 0) g_offset[N_NODES] = N_EDGES;
}

// ---------------- K4: atomic-free scatter + reset lookback state -------------
// pos = offset[dst] + rank[e]  (rank recorded by k_hist's atomic return)
__global__ void k_scatter(const int* __restrict__ ei) {
    if (blockIdx.x == 0) {
        if (threadIdx.x < N_SCAN_BLOCKS) g_state[threadIdx.x] = 0ULL;
        if (threadIdx.x == 0) g_ticket = 0;
    }
    int e = blockIdx.x * blockDim.x + threadIdx.x;
    if (e < N_EDGES) {
        int src = ei[e];
        int dst = ei[N_EDGES + e];
        g_srcsorted[g_offset[dst] + g_rank[e]] = src;
    }
}

// ---------------- K5: softmax + aggregation (half-warp/edge, ILP-4) ----------
__global__ void __launch_bounds__(256) k_aggregate(float* __restrict__ out)
{
    int warp = threadIdx.x >> 5;
    int lane = threadIdx.x & 31;
    int n = blockIdx.x * 8 + warp;
    if (n >= N_NODES) return;

    int half = lane >> 4;
    int sub  = lane & 15;
    int head = sub >> 2;

    int beg = g_offset[n];
    int end = g_offset[n + 1];

    float4 edn = *(const float4*)&g_ed[n * HEADS];
    float edh = (head == 0) ? edn.x : (head == 1) ? edn.y : (head == 2) ? edn.z : edn.w;

    float acc0 = 0.f, acc1 = 0.f, acc2 = 0.f, acc3 = 0.f;
    float acc4 = 0.f, acc5 = 0.f, acc6 = 0.f, acc7 = 0.f;
    float ssum = 0.f;

    for (int e = beg; e < end; e += 8) {
        int i0 = e + half;
        int i1 = e + 2 + half;
        int i2 = e + 4 + half;
        int i3 = e + 6 + half;
        bool b0 = i0 < end, b1 = i1 < end, b2 = i2 < end, b3 = i3 < end;
        int s0 = g_srcsorted[b0 ? i0 : beg];
        int s1 = g_srcsorted[b1 ? i1 : beg];
        int s2 = g_srcsorted[b2 ? i2 : beg];
        int s3 = g_srcsorted[b3 ? i3 : beg];
        float e0 = g_es[s0 * HEADS + head];
        float e1 = g_es[s1 * HEADS + head];
        float e2 = g_es[s2 * HEADS + head];
        float e3 = g_es[s3 * HEADS + head];
        uint4 u0 = *(const uint4*)&g_h16[s0 * HO + sub * 8];
        uint4 u1 = *(const uint4*)&g_h16[s1 * HO + sub * 8];
        uint4 u2 = *(const uint4*)&g_h16[s2 * HO + sub * 8];
        uint4 u3 = *(const uint4*)&g_h16[s3 * HO + sub * 8];

        e0 += edh; e0 = e0 >= 0.f ? e0 : NEG_SLOPE * e0;
        e1 += edh; e1 = e1 >= 0.f ? e1 : NEG_SLOPE * e1;
        e2 += edh; e2 = e2 >= 0.f ? e2 : NEG_SLOPE * e2;
        e3 += edh; e3 = e3 >= 0.f ? e3 : NEG_SLOPE * e3;
        float w0 = b0 ? __expf(e0) : 0.f;
        float w1 = b1 ? __expf(e1) : 0.f;
        float w2 = b2 ? __expf(e2) : 0.f;
        float w3 = b3 ? __expf(e3) : 0.f;
        ssum += (w0 + w1) + (w2 + w3);

        float2 f;
        f = __half22float2(*(__half2*)&u0.x); acc0 = fmaf(w0, f.x, acc0); acc1 = fmaf(w0, f.y, acc1);
        f = __half22float2(*(__half2*)&u0.y); acc2 = fmaf(w0, f.x, acc2); acc3 = fmaf(w0, f.y, acc3);
        f = __half22float2(*(__half2*)&u0.z); acc4 = fmaf(w0, f.x, acc4); acc5 = fmaf(w0, f.y, acc5);
        f = __half22float2(*(__half2*)&u0.w); acc6 = fmaf(w0, f.x, acc6); acc7 = fmaf(w0, f.y, acc7);
        f = __half22float2(*(__half2*)&u1.x); acc0 = fmaf(w1, f.x, acc0); acc1 = fmaf(w1, f.y, acc1);
        f = __half22float2(*(__half2*)&u1.y); acc2 = fmaf(w1, f.x, acc2); acc3 = fmaf(w1, f.y, acc3);
        f = __half22float2(*(__half2*)&u1.z); acc4 = fmaf(w1, f.x, acc4); acc5 = fmaf(w1, f.y, acc5);
        f = __half22float2(*(__half2*)&u1.w); acc6 = fmaf(w1, f.x, acc6); acc7 = fmaf(w1, f.y, acc7);
        f = __half22float2(*(__half2*)&u2.x); acc0 = fmaf(w2, f.x, acc0); acc1 = fmaf(w2, f.y, acc1);
        f = __half22float2(*(__half2*)&u2.y); acc2 = fmaf(w2, f.x, acc2); acc3 = fmaf(w2, f.y, acc3);
        f = __half22float2(*(__half2*)&u2.z); acc4 = fmaf(w2, f.x, acc4); acc5 = fmaf(w2, f.y, acc5);
        f = __half22float2(*(__half2*)&u2.w); acc6 = fmaf(w2, f.x, acc6); acc7 = fmaf(w2, f.y, acc7);
        f = __half22float2(*(__half2*)&u3.x); acc0 = fmaf(w3, f.x, acc0); acc1 = fmaf(w3, f.y, acc1);
        f = __half22float2(*(__half2*)&u3.y); acc2 = fmaf(w3, f.x, acc2); acc3 = fmaf(w3, f.y, acc3);
        f = __half22float2(*(__half2*)&u3.z); acc4 = fmaf(w3, f.x, acc4); acc5 = fmaf(w3, f.y, acc5);
        f = __half22float2(*(__half2*)&u3.w); acc6 = fmaf(w3, f.x, acc6); acc7 = fmaf(w3, f.y, acc7);
    }

    acc0 += __shfl_xor_sync(0xffffffffu, acc0, 16);
    acc1 += __shfl_xor_sync(0xffffffffu, acc1, 16);
    acc2 += __shfl_xor_sync(0xffffffffu, acc2, 16);
    acc3 += __shfl_xor_sync(0xffffffffu, acc3, 16);
    acc4 += __shfl_xor_sync(0xffffffffu, acc4, 16);
    acc5 += __shfl_xor_sync(0xffffffffu, acc5, 16);
    acc6 += __shfl_xor_sync(0xffffffffu, acc6, 16);
    acc7 += __shfl_xor_sync(0xffffffffu, acc7, 16);
    ssum += __shfl_xor_sync(0xffffffffu, ssum, 16);

    float inv = 1.0f / (ssum + EPS_F);
    if (half == 0) {
        float4 r0 = make_float4(acc0 * inv, acc1 * inv, acc2 * inv, acc3 * inv);
        float4 r1 = make_float4(acc4 * inv, acc5 * inv, acc6 * inv, acc7 * inv);
        *(float4*)&out[n * HO + sub * 8]     = r0;
        *(float4*)&out[n * HO + sub * 8 + 4] = r1;
    }
}

// ---------------- launch ------------------------------------------------------
extern "C" void kernel_launch(void* const* d_in, const int* in_sizes, int n_in,
                              void* d_out, int out_size)
{
    const float* x     = (const float*)d_in[0];
    const int*   ei    = (const int*)  d_in[1];
    const float* W     = (const float*)d_in[2];
    const float* a_src = (const float*)d_in[3];
    const float* a_dst = (const float*)d_in[4];
    float* out = (float*)d_out;

    cudaFuncSetAttribute(k_gemm, cudaFuncAttributeMaxDynamicSharedMemorySize,
                         SMEM_GEMM_BYTES);

    cudaStream_t s1;
    cudaStreamCreateWithFlags(&s1, cudaStreamNonBlocking);
    cudaEvent_t ev0, ev1;
    cudaEventCreateWithFlags(&ev0, cudaEventDisableTiming);
    cudaEventCreateWithFlags(&ev1, cudaEventDisableTiming);

    cudaEventRecord(ev0, 0);
    cudaStreamWaitEvent(s1, ev0, 0);

    // launch 1: projection GEMM (+logits) on main stream
    k_gemm<<<NB_GEMM, 512, SMEM_GEMM_BYTES>>>(x, W, a_src, a_dst);

    // launches 2-4: CSR build (side stream)
    k_hist   <<<NB_HIST, 256, 0, s1>>>(ei);
    k_scanlb <<<N_SCAN_BLOCKS, SCAN_B, 0, s1>>>();
    k_scatter<<<(N_EDGES + 255) / 256, 256, 0, s1>>>(ei);   // 4th: profiled
    cudaEventRecord(ev1, s1);

    // join, then launch 5: aggregate
    cudaStreamWaitEvent(0, ev1, 0);
    k_aggregate<<<(N_NODES + 7) / 8, 256>>>(out);

    cudaEventDestroy(ev0);
    cudaEventDestroy(ev1);
    cudaStreamDestroy(s1);
}